// round 1
// baseline (speedup 1.0000x reference)
#include <cuda_runtime.h>
#include <cstdint>

#define TSTEPS 512
#define BATCH  64
#define IDIM   256
#define HDIM   2048
#define NMT    16          // M tiles (H / 128)
#define NKG    9           // 8 K-slices of W_hat + 1 for W_in (input projection)
#define NCTA   (NMT*NKG)   // 144 CTAs, all co-resident (<= 148 SMs)
#define KSL    256         // K per slice
#define MT     128         // M (H rows) per CTA
#define APAD   260         // padded SMEM row stride (conflict-free frags)
#define SPAD   132         // padded stage stride
#define NTHR   256
#define SMEM_FLOATS (MT*APAD + BATCH*APAD)
#define SMEM_BYTES  (SMEM_FLOATS*4)

// Scratch (static __device__ per harness rules: no allocation anywhere)
__device__ float    g_state[BATCH*HDIM];          // current state [B,H] fp32
__device__ float    g_part[NKG*BATCH*HDIM];       // partials [kg][b][h]
__device__ unsigned g_flags[NCTA];                // barrier flags (monotonic)

__device__ __forceinline__ void mma_tf32(float* c, const uint32_t* a, const uint32_t* b) {
    asm volatile(
        "mma.sync.aligned.m16n8k8.row.col.f32.tf32.tf32.f32 "
        "{%0,%1,%2,%3}, {%4,%5,%6,%7}, {%8,%9}, {%0,%1,%2,%3};\n"
        : "+f"(c[0]), "+f"(c[1]), "+f"(c[2]), "+f"(c[3])
        : "r"(a[0]), "r"(a[1]), "r"(a[2]), "r"(a[3]), "r"(b[0]), "r"(b[1]));
}

// All-to-all flag barrier: one release store per CTA, 144 parallel pollers.
// Flags are monotonic across launches; 'base' is read (own flag only) at entry,
// and all CTAs always execute the same number of barriers, so bases agree.
__device__ __forceinline__ void gridbar(int c, unsigned base, unsigned idx) {
    const unsigned target = base + idx;
    __syncthreads();
    if (threadIdx.x == 0) {
        __threadfence();
        *(volatile unsigned*)&g_flags[c] = target;
    }
    if (threadIdx.x < NCTA) {
        while (*(volatile unsigned*)&g_flags[threadIdx.x] < target) { }
    }
    __syncthreads();
    __threadfence();
}

__global__ void __launch_bounds__(NTHR, 1)
reservoir_kernel(const float* __restrict__ x,     // [T,B,I]
                 const float* __restrict__ s0,    // [B,H]
                 const float* __restrict__ Win,   // [H,I]
                 const float* __restrict__ What,  // [H,H]
                 float* __restrict__ out)         // [T,B,H]
{
    extern __shared__ float smem[];
    float* Ws = smem;                  // [MT][APAD] weight slice (tf32-rounded)
    float* Bs = smem + MT*APAD;        // [BATCH][APAD] B tile / epilogue stage

    const int c   = blockIdx.x;
    const int tid = threadIdx.x;
    const int mt  = c % NMT;           // which 128-row H tile
    const int kg  = c / NMT;           // which K group (8 = input projection)

    const unsigned base = *(volatile unsigned*)&g_flags[c];
    unsigned bidx = 0;

    // ---- one-time: load weight slice into SMEM, RNA-rounded to tf32 ----
    {
        const float* src; int stride;
        if (kg < 8) { src = What + (size_t)mt*MT*HDIM + (size_t)kg*KSL; stride = HDIM; }
        else        { src = Win  + (size_t)mt*MT*IDIM;                  stride = IDIM; }
        for (int i = tid; i < MT*KSL; i += NTHR) {
            int r = i >> 8, cc = i & 255;
            unsigned u;
            asm("cvt.rna.tf32.f32 %0, %1;" : "=r"(u) : "f"(src[(size_t)r*stride + cc]));
            Ws[r*APAD + cc] = __uint_as_float(u);
        }
    }
    // ---- one-time: initialize state from input (deterministic each launch) ----
    if (c < 128) {
        ((float4*)g_state)[c*256 + tid] = ((const float4*)s0)[c*256 + tid];
    }
    gridbar(c, base, ++bidx);

    const int warp = tid >> 5, lane = tid & 31;
    const int gid  = lane >> 2, tig = lane & 3;     // mma fragment coords
    const int wM   = (warp >> 1) * 32;              // 4 warp-rows over M=128
    const int wN   = (warp & 1) * 32;               // 2 warp-cols over N=64

    for (int t = 0; t < TSTEPS; ++t) {
        // ---- load B tile: state slice [64, 256] (or x_t for kg==8) ----
        {
            const float* src = (kg < 8) ? (g_state + kg*KSL)
                                        : (x + (size_t)t*BATCH*IDIM);
            const int stride = (kg < 8) ? HDIM : IDIM;
            for (int i = tid; i < BATCH*64; i += NTHR) {   // 4096 float4s
                int r = i >> 6, c4 = i & 63;
                float4 v = *(const float4*)(src + (size_t)r*stride + c4*4);
                *(float4*)(Bs + r*APAD + c4*4) = v;
            }
        }
        __syncthreads();

        // ---- MMA: D[128,64] = Ws[128,256] * Bs[64,256]^T (tf32) ----
        float acc[2][4][4];
        #pragma unroll
        for (int mi = 0; mi < 2; ++mi)
            #pragma unroll
            for (int ni = 0; ni < 4; ++ni)
                #pragma unroll
                for (int q = 0; q < 4; ++q) acc[mi][ni][q] = 0.f;

        #pragma unroll 4
        for (int kk = 0; kk < KSL; kk += 8) {
            uint32_t a[2][4], b[4][2];
            #pragma unroll
            for (int mi = 0; mi < 2; ++mi) {
                const float* ap = Ws + (wM + mi*16 + gid)*APAD + kk + tig;
                a[mi][0] = __float_as_uint(ap[0]);
                a[mi][1] = __float_as_uint(ap[8*APAD]);
                a[mi][2] = __float_as_uint(ap[4]);
                a[mi][3] = __float_as_uint(ap[8*APAD + 4]);
            }
            #pragma unroll
            for (int ni = 0; ni < 4; ++ni) {
                const float* bp = Bs + (wN + ni*8 + gid)*APAD + kk + tig;
                b[ni][0] = __float_as_uint(bp[0]);
                b[ni][1] = __float_as_uint(bp[4]);
            }
            #pragma unroll
            for (int mi = 0; mi < 2; ++mi)
                #pragma unroll
                for (int ni = 0; ni < 4; ++ni)
                    mma_tf32(acc[mi][ni], a[mi], b[ni]);
        }
        __syncthreads();   // done reading Bs; reuse as transpose stage

        // ---- epilogue: transpose D to [b][h] via SMEM, write partial ----
        float* stage = Bs;
        #pragma unroll
        for (int mi = 0; mi < 2; ++mi) {
            #pragma unroll
            for (int ni = 0; ni < 4; ++ni) {
                int row = wM + mi*16 + gid;          // m (h-local)
                int col = wN + ni*8 + tig*2;         // n (batch)
                stage[(col  )*SPAD + row    ] = acc[mi][ni][0];
                stage[(col+1)*SPAD + row    ] = acc[mi][ni][1];
                stage[(col  )*SPAD + row + 8] = acc[mi][ni][2];
                stage[(col+1)*SPAD + row + 8] = acc[mi][ni][3];
            }
        }
        __syncthreads();
        {
            float* dst = g_part + (size_t)kg*BATCH*HDIM + mt*MT;
            for (int i = tid; i < BATCH*32; i += NTHR) {   // 64 rows x 32 float4
                int b = i >> 5, h4 = i & 31;
                *(float4*)(dst + (size_t)b*HDIM + h4*4) =
                    *(float4*)(stage + b*SPAD + h4*4);
            }
        }
        gridbar(c, base, ++bidx);

        // ---- finalize: sum 9 partials, tanh, leaky update, emit ----
        if (c < 128) {
            const int e = c*1024 + tid*4;           // b-major, h fastest, coalesced
            const float* pp = g_part + e;
            float4 s = *(const float4*)pp;
            #pragma unroll
            for (int k2 = 1; k2 < NKG; ++k2) {
                float4 v = *(const float4*)(pp + (size_t)k2*BATCH*HDIM);
                s.x += v.x; s.y += v.y; s.z += v.z; s.w += v.w;
            }
            float4 so = *(const float4*)(g_state + e);
            float4 sn;
            sn.x = 0.5f*(so.x + tanhf(s.x));
            sn.y = 0.5f*(so.y + tanhf(s.y));
            sn.z = 0.5f*(so.z + tanhf(s.z));
            sn.w = 0.5f*(so.w + tanhf(s.w));
            *(float4*)(g_state + e) = sn;
            *(float4*)(out + (size_t)t*BATCH*HDIM + e) = sn;
        }
        gridbar(c, base, ++bidx);
    }
}

extern "C" void kernel_launch(void* const* d_in, const int* in_sizes, int n_in,
                              void* d_out, int out_size)
{
    (void)in_sizes; (void)n_in; (void)out_size;
    const float* x    = (const float*)d_in[0];
    const float* s0   = (const float*)d_in[1];
    const float* Win  = (const float*)d_in[2];
    const float* What = (const float*)d_in[3];

    cudaFuncSetAttribute(reservoir_kernel,
                         cudaFuncAttributeMaxDynamicSharedMemorySize, SMEM_BYTES);
    reservoir_kernel<<<NCTA, NTHR, SMEM_BYTES>>>(x, s0, Win, What, (float*)d_out);
}